// round 3
// baseline (speedup 1.0000x reference)
#include <cuda_runtime.h>
#include <cuda_bf16.h>
#include <math.h>

// ---------------------------------------------------------------------------
// MnistAdditionModule: LeNet (16384 digit images) -> per-digit log-softmax
//                      -> circuit over n1+n2 sums  => out [4096, 199] fp32
// ---------------------------------------------------------------------------

#define N_IMAGES 16384
#define BATCH    4096

// intermediate buffers (static device memory; no allocations allowed)
__device__ float g_out1[N_IMAGES * 6 * 12 * 12];   // conv1+pool+relu
__device__ float g_out2[N_IMAGES * 256];           // conv2+pool+relu (flattened)
__device__ float g_lp  [N_IMAGES * 10];            // per-image log-probs

// ---------------------------------------------------------------------------
// K1: conv1 (1->6, 5x5, valid) + bias + maxpool2 + relu.  One block per image.
// ---------------------------------------------------------------------------
__global__ void conv1_kernel(const float* __restrict__ images,
                             const float* __restrict__ w,
                             const float* __restrict__ b) {
    __shared__ float img[784];
    __shared__ float ws[150];
    __shared__ float bs[6];
    int n = blockIdx.x;
    const float* im = images + n * 784;
    for (int i = threadIdx.x; i < 784; i += blockDim.x) img[i] = im[i];
    if (threadIdx.x < 150) ws[threadIdx.x] = w[threadIdx.x];
    if (threadIdx.x < 6)   bs[threadIdx.x] = b[threadIdx.x];
    __syncthreads();

    int t = threadIdx.x;
    if (t >= 144) return;
    int oh = t / 12, ow = t - oh * 12;

    // 6x6 input window covering the 2x2 pooled conv outputs
    float win[6][6];
#pragma unroll
    for (int i = 0; i < 6; i++)
#pragma unroll
        for (int j = 0; j < 6; j++)
            win[i][j] = img[(2 * oh + i) * 28 + (2 * ow + j)];

    float* out = g_out1 + n * 864 + t;
#pragma unroll
    for (int ch = 0; ch < 6; ch++) {
        float a00 = 0.f, a01 = 0.f, a10 = 0.f, a11 = 0.f;
        const float* wp = &ws[ch * 25];
#pragma unroll
        for (int i = 0; i < 5; i++)
#pragma unroll
            for (int j = 0; j < 5; j++) {
                float wv = wp[i * 5 + j];
                a00 = fmaf(win[i][j],     wv, a00);
                a01 = fmaf(win[i][j + 1], wv, a01);
                a10 = fmaf(win[i + 1][j],     wv, a10);
                a11 = fmaf(win[i + 1][j + 1], wv, a11);
            }
        float m = fmaxf(fmaxf(a00, a01), fmaxf(a10, a11)) + bs[ch];
        out[ch * 144] = fmaxf(m, 0.f);
    }
}

// ---------------------------------------------------------------------------
// K2: conv2 (6->16, 5x5, valid on 12x12) + bias + maxpool2 + relu.
// One block (256 threads) per image; thread t -> ch=t/16, pooled pos=t%16.
// ---------------------------------------------------------------------------
__global__ void conv2_kernel(const float* __restrict__ w,
                             const float* __restrict__ b) {
    __shared__ float in[864];    // 6 x 12 x 12
    __shared__ float ws[2400];   // 16 x 6 x 25
    __shared__ float bs[16];
    int n = blockIdx.x;
    for (int i = threadIdx.x; i < 864; i += 256)  in[i] = g_out1[n * 864 + i];
    for (int i = threadIdx.x; i < 2400; i += 256) ws[i] = w[i];
    if (threadIdx.x < 16) bs[threadIdx.x] = b[threadIdx.x];
    __syncthreads();

    int t  = threadIdx.x;
    int ch = t >> 4, pos = t & 15;
    int oh = pos >> 2, ow = pos & 3;

    float a00 = 0.f, a01 = 0.f, a10 = 0.f, a11 = 0.f;
#pragma unroll
    for (int ic = 0; ic < 6; ic++) {
        float win[6][6];
#pragma unroll
        for (int i = 0; i < 6; i++)
#pragma unroll
            for (int j = 0; j < 6; j++)
                win[i][j] = in[ic * 144 + (2 * oh + i) * 12 + (2 * ow + j)];
        const float* wp = &ws[(ch * 6 + ic) * 25];
#pragma unroll
        for (int i = 0; i < 5; i++)
#pragma unroll
            for (int j = 0; j < 5; j++) {
                float wv = wp[i * 5 + j];
                a00 = fmaf(win[i][j],     wv, a00);
                a01 = fmaf(win[i][j + 1], wv, a01);
                a10 = fmaf(win[i + 1][j],     wv, a10);
                a11 = fmaf(win[i + 1][j + 1], wv, a11);
            }
    }
    float m = fmaxf(fmaxf(a00, a01), fmaxf(a10, a11)) + bs[ch];
    // flattened feature index c*16 + h*4 + w == t  (NCHW reshape)
    g_out2[n * 256 + t] = fmaxf(m, 0.f);
}

// ---------------------------------------------------------------------------
// K3: fc1(256->120)+relu, fc2(120->84)+relu, fc3(84->10), log_softmax.
// All weights resident in smem (k-major so lane-j reads are conflict-free).
// 16 images per block, 1024 blocks.
// ---------------------------------------------------------------------------
#define FC_SMEM_FLOATS (30720 + 10080 + 840 + 120 + 84 + 16 + 4096 + 1920 + 1344 + 160)
#define FC_SMEM_BYTES  (FC_SMEM_FLOATS * 4)

__global__ void fc_kernel(const float* __restrict__ w1, const float* __restrict__ b1,
                          const float* __restrict__ w2, const float* __restrict__ b2,
                          const float* __restrict__ w3, const float* __restrict__ b3) {
    extern __shared__ float sm[];
    float* s_w1 = sm;              // [256][120] (k-major)
    float* s_w2 = s_w1 + 30720;    // [120][84]
    float* s_w3 = s_w2 + 10080;    // [84][10]
    float* s_b1 = s_w3 + 840;      // 120
    float* s_b2 = s_b1 + 120;      // 84
    float* s_b3 = s_b2 + 84;       // 10 (padded to 16)
    float* s_x  = s_b3 + 16;       // [16][256]
    float* s_h1 = s_x  + 4096;     // [16][120]
    float* s_h2 = s_h1 + 1920;     // [16][84]
    float* s_z  = s_h2 + 1344;     // [16][10]

    int t = threadIdx.x;           // 256 threads
    // load weights, transposed to k-major
    for (int i = t; i < 30720; i += 256)
        s_w1[(i & 255) * 120 + (i >> 8)] = w1[i];          // i = j*256 + k
    for (int i = t; i < 10080; i += 256) {
        int j = i / 120, k = i - j * 120;
        s_w2[k * 84 + j] = w2[i];
    }
    for (int i = t; i < 840; i += 256) {
        int j = i / 84, k = i - j * 84;
        s_w3[k * 10 + j] = w3[i];
    }
    if (t < 120) s_b1[t] = b1[t];
    if (t < 84)  s_b2[t] = b2[t];
    if (t < 10)  s_b3[t] = b3[t];

    int n0 = blockIdx.x * 16;
    for (int i = t; i < 4096; i += 256) s_x[i] = g_out2[n0 * 256 + i];
    __syncthreads();

    // fc1: 16*120 = 1920 dots over 256
    for (int o = t; o < 1920; o += 256) {
        int g = o / 120, j = o - g * 120;
        const float* xp = s_x + g * 256;
        float acc = s_b1[j];
#pragma unroll 8
        for (int k = 0; k < 256; k++) acc = fmaf(xp[k], s_w1[k * 120 + j], acc);
        s_h1[g * 120 + j] = fmaxf(acc, 0.f);
    }
    __syncthreads();

    // fc2: 16*84 = 1344 dots over 120
    for (int o = t; o < 1344; o += 256) {
        int g = o / 84, j = o - g * 84;
        const float* xp = s_h1 + g * 120;
        float acc = s_b2[j];
#pragma unroll 8
        for (int k = 0; k < 120; k++) acc = fmaf(xp[k], s_w2[k * 84 + j], acc);
        s_h2[g * 84 + j] = fmaxf(acc, 0.f);
    }
    __syncthreads();

    // fc3: 16*10 = 160 dots over 84
    for (int o = t; o < 160; o += 256) {
        int g = o / 10, j = o - g * 10;
        const float* xp = s_h2 + g * 84;
        float acc = s_b3[j];
#pragma unroll
        for (int k = 0; k < 84; k++) acc = fmaf(xp[k], s_w3[k * 10 + j], acc);
        s_z[o] = acc;
    }
    __syncthreads();

    // log_softmax per image
    if (t < 16) {
        const float* z = s_z + t * 10;
        float m = -1e30f;
#pragma unroll
        for (int i = 0; i < 10; i++) m = fmaxf(m, z[i]);
        float s = 0.f;
#pragma unroll
        for (int i = 0; i < 10; i++) s += __expf(z[i] - m);
        float lse = __logf(s) + m;
        float* out = g_lp + (n0 + t) * 10;
#pragma unroll
        for (int i = 0; i < 10; i++) out[i] = z[i] - lse;
    }
}

// ---------------------------------------------------------------------------
// K4: circuit. For each batch element b:
//   lp1[k] = lp[d0][k/10] + lp[d1][k%10]  (k = 0..99), same for lp2.
//   out[s] = logsumexp_{i+j=s}(lp1[i]+lp2[j])
// Computed as a linear-space convolution of the max-normalized prob vectors:
//   out[s] = log( sum_i p1[i]*p2[s-i] ) + m1 + m2   (exactly equivalent)
// ---------------------------------------------------------------------------
__global__ void circuit_kernel(float* __restrict__ out) {
    __shared__ float p1[100], p2[100];
    __shared__ float msum[2];
    int b = blockIdx.x;
    const float* lp = g_lp + b * 40;
    int t = threadIdx.x;   // 256 threads

    if (t == 0) {
        float m0 = -1e30f, m1 = -1e30f, m2 = -1e30f, m3 = -1e30f;
#pragma unroll
        for (int i = 0; i < 10; i++) {
            m0 = fmaxf(m0, lp[i]);
            m1 = fmaxf(m1, lp[10 + i]);
            m2 = fmaxf(m2, lp[20 + i]);
            m3 = fmaxf(m3, lp[30 + i]);
        }
        msum[0] = m0 + m1;
        msum[1] = m2 + m3;
    }
    __syncthreads();
    if (t < 100) {
        p1[t] = __expf(lp[t / 10] + lp[10 + t % 10] - msum[0]);
    } else if (t < 200) {
        int k = t - 100;
        p2[k] = __expf(lp[20 + k / 10] + lp[30 + k % 10] - msum[1]);
    }
    __syncthreads();
    if (t < 199) {
        int lo = max(0, t - 99), hi = min(99, t);
        float s = 0.f;
        for (int i = lo; i <= hi; i++) s = fmaf(p1[i], p2[t - i], s);
        out[b * 199 + t] = __logf(s) + msum[0] + msum[1];
    }
}

// ---------------------------------------------------------------------------
extern "C" void kernel_launch(void* const* d_in, const int* in_sizes, int n_in,
                              void* d_out, int out_size) {
    const float* images = (const float*)d_in[0];
    const float* c1w    = (const float*)d_in[1];
    const float* c1b    = (const float*)d_in[2];
    const float* c2w    = (const float*)d_in[3];
    const float* c2b    = (const float*)d_in[4];
    const float* f1w    = (const float*)d_in[5];
    const float* f1b    = (const float*)d_in[6];
    const float* f2w    = (const float*)d_in[7];
    const float* f2b    = (const float*)d_in[8];
    const float* f3w    = (const float*)d_in[9];
    const float* f3b    = (const float*)d_in[10];
    float* out = (float*)d_out;

    cudaFuncSetAttribute(fc_kernel, cudaFuncAttributeMaxDynamicSharedMemorySize,
                         FC_SMEM_BYTES);

    conv1_kernel<<<N_IMAGES, 160>>>(images, c1w, c1b);
    conv2_kernel<<<N_IMAGES, 256>>>(c2w, c2b);
    fc_kernel<<<N_IMAGES / 16, 256, FC_SMEM_BYTES>>>(f1w, f1b, f2w, f2b, f3w, f3b);
    circuit_kernel<<<BATCH, 256>>>(out);
}

// round 4
// speedup vs baseline: 1.0042x; 1.0042x over previous
#include <cuda_runtime.h>
#include <cuda_bf16.h>
#include <math.h>

// ---------------------------------------------------------------------------
// MnistAdditionModule: LeNet (16384 digit images) -> per-digit log-softmax
//                      -> circuit over n1+n2 sums  => out [4096, 199] fp32
// ---------------------------------------------------------------------------

#define N_IMAGES 16384
#define BATCH    4096

// intermediate buffers (static device memory; no allocations allowed)
__device__ float g_out1[N_IMAGES * 6 * 12 * 12];   // conv1+pool+relu
__device__ float g_out2[N_IMAGES * 256];           // conv2+pool+relu (flattened)
__device__ float g_lp  [N_IMAGES * 10];            // per-image log-probs

// ---------------------------------------------------------------------------
// K1: conv1 (1->6, 5x5, valid) + bias + maxpool2 + relu.  One block per image.
// ---------------------------------------------------------------------------
__global__ void conv1_kernel(const float* __restrict__ images,
                             const float* __restrict__ w,
                             const float* __restrict__ b) {
    __shared__ float img[784];
    __shared__ float ws[150];
    __shared__ float bs[6];
    int n = blockIdx.x;
    const float* im = images + n * 784;
    for (int i = threadIdx.x; i < 784; i += blockDim.x) img[i] = im[i];
    if (threadIdx.x < 150) ws[threadIdx.x] = w[threadIdx.x];
    if (threadIdx.x < 6)   bs[threadIdx.x] = b[threadIdx.x];
    __syncthreads();

    int t = threadIdx.x;
    if (t >= 144) return;
    int oh = t / 12, ow = t - oh * 12;

    // 6x6 input window covering the 2x2 pooled conv outputs
    float win[6][6];
#pragma unroll
    for (int i = 0; i < 6; i++)
#pragma unroll
        for (int j = 0; j < 6; j++)
            win[i][j] = img[(2 * oh + i) * 28 + (2 * ow + j)];

    float* out = g_out1 + n * 864 + t;
#pragma unroll
    for (int ch = 0; ch < 6; ch++) {
        float a00 = 0.f, a01 = 0.f, a10 = 0.f, a11 = 0.f;
        const float* wp = &ws[ch * 25];
#pragma unroll
        for (int i = 0; i < 5; i++)
#pragma unroll
            for (int j = 0; j < 5; j++) {
                float wv = wp[i * 5 + j];
                a00 = fmaf(win[i][j],     wv, a00);
                a01 = fmaf(win[i][j + 1], wv, a01);
                a10 = fmaf(win[i + 1][j],     wv, a10);
                a11 = fmaf(win[i + 1][j + 1], wv, a11);
            }
        float m = fmaxf(fmaxf(a00, a01), fmaxf(a10, a11)) + bs[ch];
        out[ch * 144] = fmaxf(m, 0.f);
    }
}

// ---------------------------------------------------------------------------
// K2: conv2 (6->16, 5x5, valid on 12x12) + bias + maxpool2 + relu.
// One block (256 threads) per image; thread t -> ch=t/16, pooled pos=t%16.
// ---------------------------------------------------------------------------
__global__ void conv2_kernel(const float* __restrict__ w,
                             const float* __restrict__ b) {
    __shared__ float in[864];    // 6 x 12 x 12
    __shared__ float ws[2400];   // 16 x 6 x 25
    __shared__ float bs[16];
    int n = blockIdx.x;
    for (int i = threadIdx.x; i < 864; i += 256)  in[i] = g_out1[n * 864 + i];
    for (int i = threadIdx.x; i < 2400; i += 256) ws[i] = w[i];
    if (threadIdx.x < 16) bs[threadIdx.x] = b[threadIdx.x];
    __syncthreads();

    int t  = threadIdx.x;
    int ch = t >> 4, pos = t & 15;
    int oh = pos >> 2, ow = pos & 3;

    float a00 = 0.f, a01 = 0.f, a10 = 0.f, a11 = 0.f;
#pragma unroll
    for (int ic = 0; ic < 6; ic++) {
        float win[6][6];
#pragma unroll
        for (int i = 0; i < 6; i++)
#pragma unroll
            for (int j = 0; j < 6; j++)
                win[i][j] = in[ic * 144 + (2 * oh + i) * 12 + (2 * ow + j)];
        const float* wp = &ws[(ch * 6 + ic) * 25];
#pragma unroll
        for (int i = 0; i < 5; i++)
#pragma unroll
            for (int j = 0; j < 5; j++) {
                float wv = wp[i * 5 + j];
                a00 = fmaf(win[i][j],     wv, a00);
                a01 = fmaf(win[i][j + 1], wv, a01);
                a10 = fmaf(win[i + 1][j],     wv, a10);
                a11 = fmaf(win[i + 1][j + 1], wv, a11);
            }
    }
    float m = fmaxf(fmaxf(a00, a01), fmaxf(a10, a11)) + bs[ch];
    // flattened feature index c*16 + h*4 + w == t  (NCHW reshape)
    g_out2[n * 256 + t] = fmaxf(m, 0.f);
}

// ---------------------------------------------------------------------------
// K3: fc1(256->120)+relu, fc2(120->84)+relu, fc3(84->10), log_softmax.
// All weights resident in smem (k-major so lane-j reads are conflict-free).
// 16 images per block, 1024 blocks.
// ---------------------------------------------------------------------------
#define FC_SMEM_FLOATS (30720 + 10080 + 840 + 120 + 84 + 16 + 4096 + 1920 + 1344 + 160)
#define FC_SMEM_BYTES  (FC_SMEM_FLOATS * 4)

__global__ void fc_kernel(const float* __restrict__ w1, const float* __restrict__ b1,
                          const float* __restrict__ w2, const float* __restrict__ b2,
                          const float* __restrict__ w3, const float* __restrict__ b3) {
    extern __shared__ float sm[];
    float* s_w1 = sm;              // [256][120] (k-major)
    float* s_w2 = s_w1 + 30720;    // [120][84]
    float* s_w3 = s_w2 + 10080;    // [84][10]
    float* s_b1 = s_w3 + 840;      // 120
    float* s_b2 = s_b1 + 120;      // 84
    float* s_b3 = s_b2 + 84;       // 10 (padded to 16)
    float* s_x  = s_b3 + 16;       // [16][256]
    float* s_h1 = s_x  + 4096;     // [16][120]
    float* s_h2 = s_h1 + 1920;     // [16][84]
    float* s_z  = s_h2 + 1344;     // [16][10]

    int t = threadIdx.x;           // 256 threads
    // load weights, transposed to k-major
    for (int i = t; i < 30720; i += 256)
        s_w1[(i & 255) * 120 + (i >> 8)] = w1[i];          // i = j*256 + k
    for (int i = t; i < 10080; i += 256) {
        int j = i / 120, k = i - j * 120;
        s_w2[k * 84 + j] = w2[i];
    }
    for (int i = t; i < 840; i += 256) {
        int j = i / 84, k = i - j * 84;
        s_w3[k * 10 + j] = w3[i];
    }
    if (t < 120) s_b1[t] = b1[t];
    if (t < 84)  s_b2[t] = b2[t];
    if (t < 10)  s_b3[t] = b3[t];

    int n0 = blockIdx.x * 16;
    for (int i = t; i < 4096; i += 256) s_x[i] = g_out2[n0 * 256 + i];
    __syncthreads();

    // fc1: 16*120 = 1920 dots over 256
    for (int o = t; o < 1920; o += 256) {
        int g = o / 120, j = o - g * 120;
        const float* xp = s_x + g * 256;
        float acc = s_b1[j];
#pragma unroll 8
        for (int k = 0; k < 256; k++) acc = fmaf(xp[k], s_w1[k * 120 + j], acc);
        s_h1[g * 120 + j] = fmaxf(acc, 0.f);
    }
    __syncthreads();

    // fc2: 16*84 = 1344 dots over 120
    for (int o = t; o < 1344; o += 256) {
        int g = o / 84, j = o - g * 84;
        const float* xp = s_h1 + g * 120;
        float acc = s_b2[j];
#pragma unroll 8
        for (int k = 0; k < 120; k++) acc = fmaf(xp[k], s_w2[k * 84 + j], acc);
        s_h2[g * 84 + j] = fmaxf(acc, 0.f);
    }
    __syncthreads();

    // fc3: 16*10 = 160 dots over 84
    for (int o = t; o < 160; o += 256) {
        int g = o / 10, j = o - g * 10;
        const float* xp = s_h2 + g * 84;
        float acc = s_b3[j];
#pragma unroll
        for (int k = 0; k < 84; k++) acc = fmaf(xp[k], s_w3[k * 10 + j], acc);
        s_z[o] = acc;
    }
    __syncthreads();

    // log_softmax per image
    if (t < 16) {
        const float* z = s_z + t * 10;
        float m = -1e30f;
#pragma unroll
        for (int i = 0; i < 10; i++) m = fmaxf(m, z[i]);
        float s = 0.f;
#pragma unroll
        for (int i = 0; i < 10; i++) s += __expf(z[i] - m);
        float lse = __logf(s) + m;
        float* out = g_lp + (n0 + t) * 10;
#pragma unroll
        for (int i = 0; i < 10; i++) out[i] = z[i] - lse;
    }
}

// ---------------------------------------------------------------------------
// K4: circuit. For each batch element b:
//   lp1[k] = lp[d0][k/10] + lp[d1][k%10]  (k = 0..99), same for lp2.
//   out[s] = logsumexp_{i+j=s}(lp1[i]+lp2[j])
// Computed as a linear-space convolution of the max-normalized prob vectors:
//   out[s] = log( sum_i p1[i]*p2[s-i] ) + m1 + m2   (exactly equivalent)
// ---------------------------------------------------------------------------
__global__ void circuit_kernel(float* __restrict__ out) {
    __shared__ float p1[100], p2[100];
    __shared__ float msum[2];
    int b = blockIdx.x;
    const float* lp = g_lp + b * 40;
    int t = threadIdx.x;   // 256 threads

    if (t == 0) {
        float m0 = -1e30f, m1 = -1e30f, m2 = -1e30f, m3 = -1e30f;
#pragma unroll
        for (int i = 0; i < 10; i++) {
            m0 = fmaxf(m0, lp[i]);
            m1 = fmaxf(m1, lp[10 + i]);
            m2 = fmaxf(m2, lp[20 + i]);
            m3 = fmaxf(m3, lp[30 + i]);
        }
        msum[0] = m0 + m1;
        msum[1] = m2 + m3;
    }
    __syncthreads();
    if (t < 100) {
        p1[t] = __expf(lp[t / 10] + lp[10 + t % 10] - msum[0]);
    } else if (t < 200) {
        int k = t - 100;
        p2[k] = __expf(lp[20 + k / 10] + lp[30 + k % 10] - msum[1]);
    }
    __syncthreads();
    if (t < 199) {
        int lo = max(0, t - 99), hi = min(99, t);
        float s = 0.f;
        for (int i = lo; i <= hi; i++) s = fmaf(p1[i], p2[t - i], s);
        out[b * 199 + t] = __logf(s) + msum[0] + msum[1];
    }
}

// ---------------------------------------------------------------------------
extern "C" void kernel_launch(void* const* d_in, const int* in_sizes, int n_in,
                              void* d_out, int out_size) {
    const float* images = (const float*)d_in[0];
    const float* c1w    = (const float*)d_in[1];
    const float* c1b    = (const float*)d_in[2];
    const float* c2w    = (const float*)d_in[3];
    const float* c2b    = (const float*)d_in[4];
    const float* f1w    = (const float*)d_in[5];
    const float* f1b    = (const float*)d_in[6];
    const float* f2w    = (const float*)d_in[7];
    const float* f2b    = (const float*)d_in[8];
    const float* f3w    = (const float*)d_in[9];
    const float* f3b    = (const float*)d_in[10];
    float* out = (float*)d_out;

    cudaFuncSetAttribute(fc_kernel, cudaFuncAttributeMaxDynamicSharedMemorySize,
                         FC_SMEM_BYTES);

    conv1_kernel<<<N_IMAGES, 160>>>(images, c1w, c1b);
    conv2_kernel<<<N_IMAGES, 256>>>(c2w, c2b);
    fc_kernel<<<N_IMAGES / 16, 256, FC_SMEM_BYTES>>>(f1w, f1b, f2w, f2b, f3w, f3b);
    circuit_kernel<<<BATCH, 256>>>(out);
}

// round 5
// speedup vs baseline: 1.5977x; 1.5909x over previous
#include <cuda_runtime.h>
#include <cuda_bf16.h>
#include <math.h>

// ---------------------------------------------------------------------------
// MnistAdditionModule: LeNet (16384 digit images) -> per-digit log-softmax
//                      -> circuit over n1+n2 sums  => out [4096, 199] fp32
// ---------------------------------------------------------------------------

#define N_IMAGES 16384
#define BATCH    4096

typedef unsigned long long u64;

// packed-f32x2 helpers (sm_100+ double-rate fp32 path; PTX-only)
__device__ __forceinline__ u64 pack_dup(float v) {
    u64 r; asm("mov.b64 %0, {%1, %1};" : "=l"(r) : "f"(v)); return r;
}
__device__ __forceinline__ void fma2(u64& c, u64 a, u64 b) {
    asm("fma.rn.f32x2 %0, %1, %2, %0;" : "+l"(c) : "l"(a), "l"(b));
}
__device__ __forceinline__ float2 unpk(u64 v) {
    float2 f; asm("mov.b64 {%0, %1}, %2;" : "=f"(f.x), "=f"(f.y) : "l"(v)); return f;
}

// intermediate buffers (static device memory; no allocations allowed)
__device__ float g_out1[N_IMAGES * 6 * 12 * 12];   // conv1+pool+relu
__device__ float g_out2[N_IMAGES * 256];           // conv2+pool+relu (flattened)
__device__ float g_lp  [N_IMAGES * 10];            // per-image log-probs

// ---------------------------------------------------------------------------
// K1: conv1 (1->6, 5x5) + bias + maxpool2 + relu.  One block per image.
// Channel pairs packed into f32x2 accumulators; weights interleaved pair-major.
// ---------------------------------------------------------------------------
__global__ void conv1_kernel(const float* __restrict__ images,
                             const float* __restrict__ w,
                             const float* __restrict__ b) {
    __shared__ float img[784];
    __shared__ __align__(8) float ws2[300];   // 3 pairs x 25 x 2 (interleaved)
    __shared__ float bs[6];
    int n = blockIdx.x;
    const float* im = images + n * 784;
    for (int i = threadIdx.x; i < 784; i += blockDim.x) img[i] = im[i];
    if (threadIdx.x < 150) {
        int ch = threadIdx.x / 25, ij = threadIdx.x % 25;
        ws2[((ch >> 1) * 25 + ij) * 2 + (ch & 1)] = w[threadIdx.x];
    }
    if (threadIdx.x < 6) bs[threadIdx.x] = b[threadIdx.x];
    __syncthreads();

    int t = threadIdx.x;
    if (t >= 144) return;
    int oh = t / 12, ow = t - oh * 12;

    // 6x6 input window, duplicated into both f32x2 lanes
    u64 win2[6][6];
#pragma unroll
    for (int i = 0; i < 6; i++)
#pragma unroll
        for (int j = 0; j < 6; j++)
            win2[i][j] = pack_dup(img[(2 * oh + i) * 28 + (2 * ow + j)]);

    float* out = g_out1 + n * 864 + t;
#pragma unroll
    for (int p = 0; p < 3; p++) {               // channel pair
        u64 a00 = 0, a01 = 0, a10 = 0, a11 = 0;
        const u64* wp = (const u64*)&ws2[p * 50];
#pragma unroll
        for (int i = 0; i < 5; i++)
#pragma unroll
            for (int j = 0; j < 5; j++) {
                u64 wv = wp[i * 5 + j];         // (w_ch_even, w_ch_odd)
                fma2(a00, win2[i][j],         wv);
                fma2(a01, win2[i][j + 1],     wv);
                fma2(a10, win2[i + 1][j],     wv);
                fma2(a11, win2[i + 1][j + 1], wv);
            }
        float2 f00 = unpk(a00), f01 = unpk(a01), f10 = unpk(a10), f11 = unpk(a11);
        float me = fmaxf(fmaxf(f00.x, f01.x), fmaxf(f10.x, f11.x)) + bs[2 * p];
        float mo = fmaxf(fmaxf(f00.y, f01.y), fmaxf(f10.y, f11.y)) + bs[2 * p + 1];
        out[(2 * p)     * 144] = fmaxf(me, 0.f);
        out[(2 * p + 1) * 144] = fmaxf(mo, 0.f);
    }
}

// ---------------------------------------------------------------------------
// K2: conv2 (6->16, 5x5 on 12x12) + bias + maxpool2 + relu.
// 128 threads = 2 images x (16 pooled positions x 2 channel-quads).
// Each thread: 4 channels (= 2 f32x2-packed pairs) at one pooled position.
// ---------------------------------------------------------------------------
__global__ void conv2_kernel(const float* __restrict__ w,
                             const float* __restrict__ b) {
    __shared__ float in[1728];                 // 2 x 6 x 12 x 12
    __shared__ __align__(8) float ws2[2400];   // 8 pairs x 6 ic x 25 x 2
    __shared__ float bs[16];
    int n0 = blockIdx.x * 2;
    for (int i = threadIdx.x; i < 1728; i += 128) in[i] = g_out1[n0 * 864 + i];
    for (int i = threadIdx.x; i < 2400; i += 128) {
        int ch = i / 150, r = i - ch * 150;
        int ic = r / 25, ij = r - ic * 25;
        ws2[(((ch >> 1) * 6 + ic) * 25 + ij) * 2 + (ch & 1)] = w[i];
    }
    if (threadIdx.x < 16) bs[threadIdx.x] = b[threadIdx.x];
    __syncthreads();

    int t = threadIdx.x;
    int img = t >> 6, local = t & 63;
    int pos = local & 15, cg = local >> 4;     // cg: channel-quad 0..3
    int oh = pos >> 2, ow = pos & 3;
    const float* inp = in + img * 864;

    u64 acc[2][4] = {};                        // [pair-in-quad][a00,a01,a10,a11]
    for (int ic = 0; ic < 6; ic++) {
        u64 win2[6][6];
#pragma unroll
        for (int i = 0; i < 6; i++)
#pragma unroll
            for (int j = 0; j < 6; j++)
                win2[i][j] = pack_dup(inp[ic * 144 + (2 * oh + i) * 12 + (2 * ow + j)]);
#pragma unroll
        for (int q = 0; q < 2; q++) {
            int p = cg * 2 + q;
            const u64* wp = (const u64*)&ws2[((p * 6 + ic) * 25) * 2];
#pragma unroll
            for (int i = 0; i < 5; i++)
#pragma unroll
                for (int j = 0; j < 5; j++) {
                    u64 wv = wp[i * 5 + j];
                    fma2(acc[q][0], win2[i][j],         wv);
                    fma2(acc[q][1], win2[i][j + 1],     wv);
                    fma2(acc[q][2], win2[i + 1][j],     wv);
                    fma2(acc[q][3], win2[i + 1][j + 1], wv);
                }
        }
    }
    float* out = g_out2 + (n0 + img) * 256;
#pragma unroll
    for (int q = 0; q < 2; q++) {
        float2 f0 = unpk(acc[q][0]), f1 = unpk(acc[q][1]);
        float2 f2 = unpk(acc[q][2]), f3 = unpk(acc[q][3]);
        int che = cg * 4 + 2 * q;
        float me = fmaxf(fmaxf(f0.x, f1.x), fmaxf(f2.x, f3.x)) + bs[che];
        float mo = fmaxf(fmaxf(f0.y, f1.y), fmaxf(f2.y, f3.y)) + bs[che + 1];
        out[che * 16 + pos]       = fmaxf(me, 0.f);
        out[(che + 1) * 16 + pos] = fmaxf(mo, 0.f);
    }
}

// ---------------------------------------------------------------------------
// K3: fc1(256->120)+relu, fc2(120->84)+relu, fc3(84->10), log_softmax.
// 32 images/block, 256 threads. 4x4 register tiles (4 images x 4 outputs)
// cut LDS traffic from 8 B/MAC to 2 B/MAC. Weights k-major in smem with
// odd row strides (121/85) so transposed stores AND tiled loads are
// bank-conflict-free. h2/z alias the dead x region to fit 227 KB smem.
// ---------------------------------------------------------------------------
#define FC_SMEM_FLOATS (30976 + 10200 + 840 + 120 + 84 + 16 + 8192 + 3840)
#define FC_SMEM_BYTES  (FC_SMEM_FLOATS * 4)

__global__ void fc_kernel(const float* __restrict__ w1, const float* __restrict__ b1,
                          const float* __restrict__ w2, const float* __restrict__ b2,
                          const float* __restrict__ w3, const float* __restrict__ b3) {
    extern __shared__ float sm[];
    float* s_w1 = sm;              // [256][121] k-major, padded
    float* s_w2 = s_w1 + 30976;    // [120][85]  k-major, padded
    float* s_w3 = s_w2 + 10200;    // [84][10]   k-major
    float* s_b1 = s_w3 + 840;      // 120
    float* s_b2 = s_b1 + 120;      // 84
    float* s_b3 = s_b2 + 84;       // 16
    float* s_x  = s_b3 + 16;       // [32][256]; later aliased by h2, z
    float* s_h1 = s_x  + 8192;     // [32][120]
    float* s_h2 = s_x;             // [32][84]  (x dead after fc1)
    float* s_z  = s_x + 4096;      // [32][10]

    int t = threadIdx.x;           // 256 threads
    for (int i = t; i < 30720; i += 256) {
        int j = i >> 8, k = i & 255;                 // w1 is [120][256]
        s_w1[k * 121 + j] = w1[i];
    }
    for (int i = t; i < 10080; i += 256) {
        int j = i / 120, k = i - j * 120;
        s_w2[k * 85 + j] = w2[i];
    }
    for (int i = t; i < 840; i += 256) {
        int j = i / 84, k = i - j * 84;
        s_w3[k * 10 + j] = w3[i];
    }
    if (t < 120) s_b1[t] = b1[t];
    if (t < 84)  s_b2[t] = b2[t];
    if (t < 16)  s_b3[t] = (t < 10) ? b3[t] : 0.f;

    int n0 = blockIdx.x * 32;
    for (int i = t; i < 8192; i += 256) s_x[i] = g_out2[n0 * 256 + i];
    __syncthreads();

    int gg = t >> 5, jj = t & 31;   // warp = one image-quad -> x reads broadcast

    // fc1: 4 images x 4 outputs per thread (j = jj + 30u), jj < 30
    if (jj < 30) {
        float acc[4][4];
#pragma unroll
        for (int u = 0; u < 4; u++) {
            float bv = s_b1[jj + 30 * u];
#pragma unroll
            for (int gi = 0; gi < 4; gi++) acc[gi][u] = bv;
        }
        const float* xb = s_x + gg * 1024;
#pragma unroll 4
        for (int k = 0; k < 256; k++) {
            float x0 = xb[k], x1 = xb[k + 256], x2 = xb[k + 512], x3 = xb[k + 768];
            const float* wr = s_w1 + k * 121 + jj;
            float wa = wr[0], wb = wr[30], wc = wr[60], wd = wr[90];
            acc[0][0] = fmaf(x0, wa, acc[0][0]); acc[0][1] = fmaf(x0, wb, acc[0][1]);
            acc[0][2] = fmaf(x0, wc, acc[0][2]); acc[0][3] = fmaf(x0, wd, acc[0][3]);
            acc[1][0] = fmaf(x1, wa, acc[1][0]); acc[1][1] = fmaf(x1, wb, acc[1][1]);
            acc[1][2] = fmaf(x1, wc, acc[1][2]); acc[1][3] = fmaf(x1, wd, acc[1][3]);
            acc[2][0] = fmaf(x2, wa, acc[2][0]); acc[2][1] = fmaf(x2, wb, acc[2][1]);
            acc[2][2] = fmaf(x2, wc, acc[2][2]); acc[2][3] = fmaf(x2, wd, acc[2][3]);
            acc[3][0] = fmaf(x3, wa, acc[3][0]); acc[3][1] = fmaf(x3, wb, acc[3][1]);
            acc[3][2] = fmaf(x3, wc, acc[3][2]); acc[3][3] = fmaf(x3, wd, acc[3][3]);
        }
#pragma unroll
        for (int gi = 0; gi < 4; gi++)
#pragma unroll
            for (int u = 0; u < 4; u++)
                s_h1[(gg * 4 + gi) * 120 + jj + 30 * u] = fmaxf(acc[gi][u], 0.f);
    }
    __syncthreads();

    // fc2: 4 images x 4 outputs (j = jj + 21u), jj < 21. Writes alias x region.
    if (jj < 21) {
        float acc[4][4];
#pragma unroll
        for (int u = 0; u < 4; u++) {
            float bv = s_b2[jj + 21 * u];
#pragma unroll
            for (int gi = 0; gi < 4; gi++) acc[gi][u] = bv;
        }
        const float* xb = s_h1 + gg * 480;
#pragma unroll 4
        for (int k = 0; k < 120; k++) {
            float x0 = xb[k], x1 = xb[k + 120], x2 = xb[k + 240], x3 = xb[k + 360];
            const float* wr = s_w2 + k * 85 + jj;
            float wa = wr[0], wb = wr[21], wc = wr[42], wd = wr[63];
            acc[0][0] = fmaf(x0, wa, acc[0][0]); acc[0][1] = fmaf(x0, wb, acc[0][1]);
            acc[0][2] = fmaf(x0, wc, acc[0][2]); acc[0][3] = fmaf(x0, wd, acc[0][3]);
            acc[1][0] = fmaf(x1, wa, acc[1][0]); acc[1][1] = fmaf(x1, wb, acc[1][1]);
            acc[1][2] = fmaf(x1, wc, acc[1][2]); acc[1][3] = fmaf(x1, wd, acc[1][3]);
            acc[2][0] = fmaf(x2, wa, acc[2][0]); acc[2][1] = fmaf(x2, wb, acc[2][1]);
            acc[2][2] = fmaf(x2, wc, acc[2][2]); acc[2][3] = fmaf(x2, wd, acc[2][3]);
            acc[3][0] = fmaf(x3, wa, acc[3][0]); acc[3][1] = fmaf(x3, wb, acc[3][1]);
            acc[3][2] = fmaf(x3, wc, acc[3][2]); acc[3][3] = fmaf(x3, wd, acc[3][3]);
        }
#pragma unroll
        for (int gi = 0; gi < 4; gi++)
#pragma unroll
            for (int u = 0; u < 4; u++)
                s_h2[(gg * 4 + gi) * 84 + jj + 21 * u] = fmaxf(acc[gi][u], 0.f);
    }
    __syncthreads();

    // fc3: 32 img x 10 outputs = 320 dots over 84 (tiny)
    for (int o = t; o < 320; o += 256) {
        int g = o / 10, j = o - g * 10;
        const float* xp = s_h2 + g * 84;
        float acc = s_b3[j];
#pragma unroll
        for (int k = 0; k < 84; k++) acc = fmaf(xp[k], s_w3[k * 10 + j], acc);
        s_z[o] = acc;
    }
    __syncthreads();

    // log_softmax per image
    if (t < 32) {
        const float* z = s_z + t * 10;
        float m = -1e30f;
#pragma unroll
        for (int i = 0; i < 10; i++) m = fmaxf(m, z[i]);
        float s = 0.f;
#pragma unroll
        for (int i = 0; i < 10; i++) s += __expf(z[i] - m);
        float lse = __logf(s) + m;
        float* out = g_lp + (n0 + t) * 10;
#pragma unroll
        for (int i = 0; i < 10; i++) out[i] = z[i] - lse;
    }
}

// ---------------------------------------------------------------------------
// K4: circuit. out[s] = log( sum_i p1[i]*p2[s-i] ) + m1 + m2  (exact
// linear-space equivalent of the grouped logsumexp).
// ---------------------------------------------------------------------------
__global__ void circuit_kernel(float* __restrict__ out) {
    __shared__ float p1[100], p2[100];
    __shared__ float msum[2];
    int b = blockIdx.x;
    const float* lp = g_lp + b * 40;
    int t = threadIdx.x;   // 256 threads

    if (t == 0) {
        float m0 = -1e30f, m1 = -1e30f, m2 = -1e30f, m3 = -1e30f;
#pragma unroll
        for (int i = 0; i < 10; i++) {
            m0 = fmaxf(m0, lp[i]);
            m1 = fmaxf(m1, lp[10 + i]);
            m2 = fmaxf(m2, lp[20 + i]);
            m3 = fmaxf(m3, lp[30 + i]);
        }
        msum[0] = m0 + m1;
        msum[1] = m2 + m3;
    }
    __syncthreads();
    if (t < 100) {
        p1[t] = __expf(lp[t / 10] + lp[10 + t % 10] - msum[0]);
    } else if (t < 200) {
        int k = t - 100;
        p2[k] = __expf(lp[20 + k / 10] + lp[30 + k % 10] - msum[1]);
    }
    __syncthreads();
    if (t < 199) {
        int lo = max(0, t - 99), hi = min(99, t);
        float s = 0.f;
        for (int i = lo; i <= hi; i++) s = fmaf(p1[i], p2[t - i], s);
        out[b * 199 + t] = __logf(s) + msum[0] + msum[1];
    }
}

// ---------------------------------------------------------------------------
extern "C" void kernel_launch(void* const* d_in, const int* in_sizes, int n_in,
                              void* d_out, int out_size) {
    const float* images = (const float*)d_in[0];
    const float* c1w    = (const float*)d_in[1];
    const float* c1b    = (const float*)d_in[2];
    const float* c2w    = (const float*)d_in[3];
    const float* c2b    = (const float*)d_in[4];
    const float* f1w    = (const float*)d_in[5];
    const float* f1b    = (const float*)d_in[6];
    const float* f2w    = (const float*)d_in[7];
    const float* f2b    = (const float*)d_in[8];
    const float* f3w    = (const float*)d_in[9];
    const float* f3b    = (const float*)d_in[10];
    float* out = (float*)d_out;

    cudaFuncSetAttribute(fc_kernel, cudaFuncAttributeMaxDynamicSharedMemorySize,
                         FC_SMEM_BYTES);

    conv1_kernel<<<N_IMAGES, 160>>>(images, c1w, c1b);
    conv2_kernel<<<N_IMAGES / 2, 128>>>(c2w, c2b);
    fc_kernel<<<N_IMAGES / 32, 256, FC_SMEM_BYTES>>>(f1w, f1b, f2w, f2b, f3w, f3b);
    circuit_kernel<<<BATCH, 256>>>(out);
}